// round 10
// baseline (speedup 1.0000x reference)
#include <cuda_runtime.h>
#include <cuda_bf16.h>
#include <math.h>

#define N_TOK   131072
#define K_CODES 512
#define DIM     64
#define M_ELEMS (N_TOK * DIM)
#define TPB     256
#define TOKCTA  256
#define NCTA    (N_TOK / TOKCTA)     // 512
#define MARGIN  3.0e-3f              // >= 2x worst-case bf16 scoring error
#define CAP     16

// SMEM byte offsets (rows padded to 144B -> ldmatrix conflict-free)
#define SM_A    0                    // A tile: 256 rows x 144B (36864)
#define SM_B    36864                // B tile: 512 rows x 144B (73728)
#define SM_C    110592               // C fp32[512]
#define SM_H    112640               // hist u32[512]
#define SM_CNT  114688               // cand count u32[256]
#define SM_CK   115712               // cand k i32[256][16] (16384)
#define SM_SX   132096               // sidx i32[256]
#define SM_AX   133120               // exact A fp32[256]
#define SM_TOT  134144

__device__ float    g_sumsq;               // zeroed at load; final kernel re-zeroes
__device__ unsigned g_counts[K_CODES];
__device__ unsigned g_wb16[K_CODES * 32];  // bf16x2 of (-2*w), pairs along d
__device__ float    g_C[K_CODES];          // exact ||w_k||^2 (sequential rounded)

__device__ __forceinline__ void ldsm4(unsigned* r, unsigned addr) {
    asm volatile("ldmatrix.sync.aligned.m8n8.x4.shared.b16 {%0,%1,%2,%3}, [%4];"
                 : "=r"(r[0]), "=r"(r[1]), "=r"(r[2]), "=r"(r[3]) : "r"(addr));
}
__device__ __forceinline__ void mma16816(float* c, const unsigned* a,
                                         unsigned b0, unsigned b1) {
    asm volatile("mma.sync.aligned.m16n8k16.row.col.f32.bf16.bf16.f32 "
                 "{%0,%1,%2,%3}, {%4,%5,%6,%7}, {%8,%9}, {%0,%1,%2,%3};"
                 : "+f"(c[0]), "+f"(c[1]), "+f"(c[2]), "+f"(c[3])
                 : "r"(a[0]), "r"(a[1]), "r"(a[2]), "r"(a[3]), "r"(b0), "r"(b1));
}

// ------------- setup: parallel (16 blocks x 32 thr, 1 thread = 1 code) -------------
__global__ void vq_setup(const float* __restrict__ wt) {
    int k = blockIdx.x * 32 + threadIdx.x;   // 512 codes
    float4 w4[16];
    const float4* wr = (const float4*)(wt + k * DIM);
    #pragma unroll
    for (int q = 0; q < 16; q++) w4[q] = wr[q];
    float s = 0.0f;
    #pragma unroll
    for (int q = 0; q < 16; q++) {           // exact: sequential rounded, d ascending
        s = __fadd_rn(s, __fmul_rn(w4[q].x, w4[q].x));
        s = __fadd_rn(s, __fmul_rn(w4[q].y, w4[q].y));
        s = __fadd_rn(s, __fmul_rn(w4[q].z, w4[q].z));
        s = __fadd_rn(s, __fmul_rn(w4[q].w, w4[q].w));
    }
    g_C[k] = s;
    #pragma unroll
    for (int q = 0; q < 16; q++) {
        __nv_bfloat162 p0 = __floats2bfloat162_rn(-2.0f * w4[q].x, -2.0f * w4[q].y);
        __nv_bfloat162 p1 = __floats2bfloat162_rn(-2.0f * w4[q].z, -2.0f * w4[q].w);
        g_wb16[k * 32 + 2 * q]     = *(unsigned*)&p0;
        g_wb16[k * 32 + 2 * q + 1] = *(unsigned*)&p1;
    }
}

// per-n-tile score computation: 8 scores (2 m-tiles x {2 rows x 2 cols})
__device__ __forceinline__ void score_nt(int nt, const unsigned (&af)[2][4][4],
                                         unsigned sbase, const float2* sC2,
                                         int lane, float* s) {
    unsigned bf[8];
    unsigned ba = sbase + SM_B + (unsigned)(nt * 8 + (lane & 7)) * 144u
                  + (unsigned)((lane >> 3) & 3) * 16u;
    ldsm4(bf, ba);           // k 0..31
    ldsm4(bf + 4, ba + 64);  // k 32..63
    float2 cv = sC2[nt * 4 + (lane & 3)];
    float c0[4] = {cv.x, cv.y, cv.x, cv.y};
    float c1[4] = {cv.x, cv.y, cv.x, cv.y};
    #pragma unroll
    for (int kt = 0; kt < 4; kt++) {
        mma16816(c0, af[0][kt], bf[2 * kt], bf[2 * kt + 1]);
        mma16816(c1, af[1][kt], bf[2 * kt], bf[2 * kt + 1]);
    }
    s[0] = c0[0]; s[1] = c0[1]; s[2] = c0[2]; s[3] = c0[3];
    s[4] = c1[0]; s[5] = c1[1]; s[6] = c1[2]; s[7] = c1[3];
}

// ---------------- main: single fused scoring pass ----------------
extern "C" __global__ void __launch_bounds__(TPB, 1)
vq_main(const float* __restrict__ in, const float* __restrict__ wt,
        float* __restrict__ out)
{
    extern __shared__ char smem[];
    const unsigned sbase = (unsigned)__cvta_generic_to_shared(smem);
    const int tid = threadIdx.x, wid = tid >> 5, lane = tid & 31;
    const int tok0 = blockIdx.x * TOKCTA;

    float*    sC   = (float*)(smem + SM_C);
    unsigned* sH   = (unsigned*)(smem + SM_H);
    unsigned* sCnt = (unsigned*)(smem + SM_CNT);
    int*      sCk  = (int*)(smem + SM_CK);
    int*      sSx  = (int*)(smem + SM_SX);
    float*    sAx  = (float*)(smem + SM_AX);

    // ---- stage: token tid -> A-tile row tid (bf16), exact A = sum x^2 ----
    {
        const int t = tok0 + tid, b = t >> 12, hw = t & 4095;
        const float* xp = in + (b << 18) + hw;
        float A = 0.0f;
        #pragma unroll
        for (int dd = 0; dd < 32; dd++) {
            float f0 = xp[(2 * dd) << 12];
            float f1 = xp[(2 * dd + 1) << 12];
            A = __fadd_rn(A, __fmul_rn(f0, f0));
            A = __fadd_rn(A, __fmul_rn(f1, f1));
            __nv_bfloat162 p = __floats2bfloat162_rn(f0, f1);
            *(unsigned*)(smem + SM_A + tid * 144 + dd * 4) = *(unsigned*)&p;
        }
        sAx[tid] = A;
    }
    // ---- stage B (pre-packed bf16(-2w)) + C + zero hist/counters ----
    for (int i = tid; i < K_CODES * 32; i += TPB) {
        int k = i >> 5, dd = i & 31;
        *(unsigned*)(smem + SM_B + k * 144 + dd * 4) = g_wb16[i];
    }
    for (int i = tid; i < K_CODES; i += TPB) { sC[i] = g_C[i]; sH[i] = 0u; }
    sCnt[tid] = 0u;
    __syncthreads();

    // ---- load A fragments once (warp: tokens wid*32 .. +31) ----
    const int wbase = wid * 32;
    unsigned af[2][4][4];
    #pragma unroll
    for (int mt = 0; mt < 2; mt++)
        #pragma unroll
        for (int kt = 0; kt < 4; kt++) {
            unsigned aa = sbase + SM_A
                        + (unsigned)(wbase + mt * 16 + (lane & 15)) * 144u
                        + (unsigned)(kt * 32 + ((lane >> 4) & 1) * 16);
            ldsm4(af[mt][kt], aa);
        }

    const float2* sC2 = (const float2*)(smem + SM_C);
    const int r0 = lane >> 2;
    const int tA = wbase + r0, tB = tA + 8, tC = wbase + 16 + r0, tD = tC + 8;

    // ---- single fused pass: running-min thresholds + candidate pushes ----
    float rm[4];
    #define SHARE_RM()                                                      \
        { _Pragma("unroll")                                                 \
          for (int i_ = 0; i_ < 4; i_++) {                                  \
              rm[i_] = fminf(rm[i_], __shfl_xor_sync(0xffffffffu, rm[i_], 1)); \
              rm[i_] = fminf(rm[i_], __shfl_xor_sync(0xffffffffu, rm[i_], 2)); \
          } }
    #define PUSH(val, thr, tok, kk)                                         \
        if ((val) < (thr)) {                                                \
            unsigned p_ = atomicAdd(&sCnt[tok], 1u);                        \
            if (p_ < CAP) sCk[(tok) * CAP + p_] = (kk);                     \
        }
    #define PUSH8(s_, k0_)                                                  \
        PUSH(s_[0], rm[0] + MARGIN, tA, (k0_))                              \
        PUSH(s_[1], rm[0] + MARGIN, tA, (k0_) + 1)                          \
        PUSH(s_[2], rm[1] + MARGIN, tB, (k0_))                              \
        PUSH(s_[3], rm[1] + MARGIN, tB, (k0_) + 1)                          \
        PUSH(s_[4], rm[2] + MARGIN, tC, (k0_))                              \
        PUSH(s_[5], rm[2] + MARGIN, tC, (k0_) + 1)                          \
        PUSH(s_[6], rm[3] + MARGIN, tD, (k0_))                              \
        PUSH(s_[7], rm[3] + MARGIN, tD, (k0_) + 1)
    #define UPDRM(s_)                                                       \
        rm[0] = fminf(rm[0], fminf(s_[0], s_[1]));                          \
        rm[1] = fminf(rm[1], fminf(s_[2], s_[3]));                          \
        rm[2] = fminf(rm[2], fminf(s_[4], s_[5]));                          \
        rm[3] = fminf(rm[3], fminf(s_[6], s_[7]));

    {   // nt = 0: update mins, share, THEN retro-push vs shared threshold
        float s[8];
        score_nt(0, af, sbase, sC2, lane, s);
        rm[0] = fminf(s[0], s[1]);
        rm[1] = fminf(s[2], s[3]);
        rm[2] = fminf(s[4], s[5]);
        rm[3] = fminf(s[6], s[7]);
        SHARE_RM();
        const int k0 = 2 * (lane & 3);
        PUSH8(s, k0)
    }
    for (int nt = 1; nt < 64; nt++) {
        float s[8];
        score_nt(nt, af, sbase, sC2, lane, s);
        const int k0 = nt * 8 + 2 * (lane & 3);
        PUSH8(s, k0)          // push before min-update (new min still pushed)
        UPDRM(s)
        if ((nt < 16 && (nt & 3) == 3) || (nt & 7) == 7) SHARE_RM();
    }
    #undef PUSH8
    #undef PUSH
    #undef UPDRM
    #undef SHARE_RM
    __syncthreads();

    // ---- exact refinement: token tid, reference-rounded distances ----
    {
        const int t = tok0 + tid, b = t >> 12, hw = t & 4095;
        const float* xp = in + (b << 18) + hw;
        float x[DIM];
        #pragma unroll
        for (int d = 0; d < DIM; d++) x[d] = xp[d << 12];
        const float A = sAx[tid];

        float bestd = 3.4e38f;
        int   bidx  = 1 << 30;
        const unsigned cn = sCnt[tid];

        #define EXACT(kk)                                                  \
        {                                                                  \
            const float4* wr = (const float4*)(wt + (kk) * DIM);           \
            float dot = 0.0f;                                              \
            _Pragma("unroll")                                              \
            for (int q = 0; q < 16; q++) {                                 \
                float4 v = wr[q];                                          \
                dot = __fmaf_rn(x[4 * q],     v.x, dot);                   \
                dot = __fmaf_rn(x[4 * q + 1], v.y, dot);                   \
                dot = __fmaf_rn(x[4 * q + 2], v.z, dot);                   \
                dot = __fmaf_rn(x[4 * q + 3], v.w, dot);                   \
            }                                                              \
            float dist = __fadd_rn(__fadd_rn(A, -2.0f * dot), sC[kk]);     \
            if (dist < bestd || (dist == bestd && (kk) < bidx)) {          \
                bestd = dist; bidx = (kk);                                 \
            }                                                              \
        }
        if (cn <= CAP) {
            for (unsigned c = 0; c < cn; c++) { int k = sCk[tid * CAP + c]; EXACT(k) }
        } else {
            for (int k = 0; k < K_CODES; k++) EXACT(k)   // sound fallback
        }
        #undef EXACT
        sSx[tid] = bidx;
        atomicAdd(&sH[bidx], 1u);
    }
    __syncthreads();

    // ---- output (linear-view quirk) + loss partial ----
    float lsum = 0.0f;
    const long ob = (long)tok0 * DIM;
    for (int i = tid; i < TOKCTA * DIM; i += TPB) {
        int   tk = i >> 6, d = i & 63;
        int   k  = sSx[tk];
        float q  = wt[k * DIM + d];
        float xv = in[ob + i];
        out[ob + i] = q;
        float df = q - xv;
        lsum = fmaf(df, df, lsum);
    }
    #pragma unroll
    for (int o = 16; o > 0; o >>= 1) lsum += __shfl_xor_sync(0xffffffffu, lsum, o);
    float* red = (float*)(smem + SM_CK);   // candidates dead; reuse as scratch
    __syncthreads();
    if (lane == 0) red[wid] = lsum;
    __syncthreads();
    if (tid == 0) {
        float v = 0.0f;
        #pragma unroll
        for (int w = 0; w < 8; w++) v += red[w];
        atomicAdd(&g_sumsq, v);
    }
    for (int k = tid; k < K_CODES; k += TPB) {
        unsigned c = sH[k];
        if (c) atomicAdd(&g_counts[k], c);
    }
}

// ---------------- final: loss + perplexity + replay reset ----------------
__global__ void vq_final_kernel(float* __restrict__ out) {
    int t = threadIdx.x;  // 512 threads
    float p    = (float)g_counts[t] * (1.0f / (float)N_TOK);
    float term = p * logf(p + 1e-10f);
    #pragma unroll
    for (int o = 16; o > 0; o >>= 1) term += __shfl_xor_sync(0xffffffffu, term, o);
    __shared__ float r[16];
    if ((t & 31) == 0) r[t >> 5] = term;
    __syncthreads();
    if (t < 16) {
        float v = r[t];
        #pragma unroll
        for (int o = 8; o > 0; o >>= 1) v += __shfl_xor_sync(0x0000ffffu, v, o);
        if (t == 0) {
            out[M_ELEMS]     = 1.25f * (g_sumsq * (1.0f / (float)M_ELEMS));
            out[M_ELEMS + 1] = expf(-v);
            g_sumsq = 0.0f;
        }
    }
    g_counts[t] = 0u;
}

extern "C" void kernel_launch(void* const* d_in, const int* in_sizes, int n_in,
                              void* d_out, int out_size)
{
    const float* in  = (const float*)d_in[0];
    const float* wt  = (const float*)d_in[1];
    float*       out = (float*)d_out;

    cudaFuncSetAttribute(vq_main, cudaFuncAttributeMaxDynamicSharedMemorySize, SM_TOT);

    vq_setup<<<16, 32>>>(wt);
    vq_main<<<NCTA, TPB, SM_TOT>>>(in, wt, out);
    vq_final_kernel<<<1, 512>>>(out);
}

// round 11
// speedup vs baseline: 5.6782x; 5.6782x over previous
#include <cuda_runtime.h>
#include <cuda_bf16.h>
#include <math.h>

#define N_TOK   131072
#define K_CODES 512
#define DIM     64
#define M_ELEMS (N_TOK * DIM)
#define TPB     256
#define TOKCTA  256
#define NCTA    (N_TOK / TOKCTA)     // 512
#define MARGIN  3.0e-3f              // >= 2x worst-case bf16 scoring error
#define CAP     16

// SMEM byte offsets (rows padded to 144B -> ldmatrix conflict-free)
#define SM_A    0                    // A tile: 256 rows x 144B (36864)
#define SM_B    36864                // B tile: 512 rows x 144B (73728)
#define SM_C    110592               // C fp32[512]
#define SM_H    112640               // hist u32[512]
#define SM_CNT  114688               // cand count u32[256]
#define SM_CK   115712               // cand k i32[256][16] (16384)
#define SM_SX   132096               // sidx i32[256]
#define SM_AX   133120               // exact A fp32[256]
#define SM_TOT  134144

__device__ float    g_sumsq;               // zeroed at load; last CTA re-zeroes
__device__ unsigned g_counts[K_CODES];
__device__ unsigned g_done;                // completion counter (last-CTA pattern)
__device__ unsigned g_wb16[K_CODES * 32];  // bf16x2 of (-2*w), pairs along d
__device__ float    g_C[K_CODES];          // exact ||w_k||^2 (sequential rounded)

__device__ __forceinline__ void ldsm4(unsigned* r, unsigned addr) {
    asm volatile("ldmatrix.sync.aligned.m8n8.x4.shared.b16 {%0,%1,%2,%3}, [%4];"
                 : "=r"(r[0]), "=r"(r[1]), "=r"(r[2]), "=r"(r[3]) : "r"(addr));
}
__device__ __forceinline__ void mma16816(float* c, const unsigned* a,
                                         unsigned b0, unsigned b1) {
    asm volatile("mma.sync.aligned.m16n8k16.row.col.f32.bf16.bf16.f32 "
                 "{%0,%1,%2,%3}, {%4,%5,%6,%7}, {%8,%9}, {%0,%1,%2,%3};"
                 : "+f"(c[0]), "+f"(c[1]), "+f"(c[2]), "+f"(c[3])
                 : "r"(a[0]), "r"(a[1]), "r"(a[2]), "r"(a[3]), "r"(b0), "r"(b1));
}

// ------------- setup: parallel (16 blocks x 32 thr, 1 thread = 1 code) -------------
__global__ void vq_setup(const float* __restrict__ wt) {
    int k = blockIdx.x * 32 + threadIdx.x;   // 512 codes
    float4 w4[16];
    const float4* wr = (const float4*)(wt + k * DIM);
    #pragma unroll
    for (int q = 0; q < 16; q++) w4[q] = wr[q];
    float s = 0.0f;
    #pragma unroll
    for (int q = 0; q < 16; q++) {           // exact: sequential rounded, d ascending
        s = __fadd_rn(s, __fmul_rn(w4[q].x, w4[q].x));
        s = __fadd_rn(s, __fmul_rn(w4[q].y, w4[q].y));
        s = __fadd_rn(s, __fmul_rn(w4[q].z, w4[q].z));
        s = __fadd_rn(s, __fmul_rn(w4[q].w, w4[q].w));
    }
    g_C[k] = s;
    #pragma unroll
    for (int q = 0; q < 16; q++) {
        __nv_bfloat162 p0 = __floats2bfloat162_rn(-2.0f * w4[q].x, -2.0f * w4[q].y);
        __nv_bfloat162 p1 = __floats2bfloat162_rn(-2.0f * w4[q].z, -2.0f * w4[q].w);
        g_wb16[k * 32 + 2 * q]     = *(unsigned*)&p0;
        g_wb16[k * 32 + 2 * q + 1] = *(unsigned*)&p1;
    }
}

// per-n-tile score computation: 8 scores (2 m-tiles x {2 rows x 2 cols})
__device__ __forceinline__ void score_nt(int nt, const unsigned (&af)[2][4][4],
                                         unsigned sbase, const float2* sC2,
                                         int lane, float* s) {
    unsigned bf[8];
    unsigned ba = sbase + SM_B + (unsigned)(nt * 8 + (lane & 7)) * 144u
                  + (unsigned)((lane >> 3) & 3) * 16u;
    ldsm4(bf, ba);           // k 0..31
    ldsm4(bf + 4, ba + 64);  // k 32..63
    float2 cv = sC2[nt * 4 + (lane & 3)];
    float c0[4] = {cv.x, cv.y, cv.x, cv.y};
    float c1[4] = {cv.x, cv.y, cv.x, cv.y};
    #pragma unroll
    for (int kt = 0; kt < 4; kt++) {
        mma16816(c0, af[0][kt], bf[2 * kt], bf[2 * kt + 1]);
        mma16816(c1, af[1][kt], bf[2 * kt], bf[2 * kt + 1]);
    }
    s[0] = c0[0]; s[1] = c0[1]; s[2] = c0[2]; s[3] = c0[3];
    s[4] = c1[0]; s[5] = c1[1]; s[6] = c1[2]; s[7] = c1[3];
}

// ---------------- main (R9 two-pass scoring + fused final) ----------------
extern "C" __global__ void __launch_bounds__(TPB, 1)
vq_main(const float* __restrict__ in, const float* __restrict__ wt,
        float* __restrict__ out)
{
    extern __shared__ char smem[];
    const unsigned sbase = (unsigned)__cvta_generic_to_shared(smem);
    const int tid = threadIdx.x, wid = tid >> 5, lane = tid & 31;
    const int tok0 = blockIdx.x * TOKCTA;

    float*    sC   = (float*)(smem + SM_C);
    unsigned* sH   = (unsigned*)(smem + SM_H);
    unsigned* sCnt = (unsigned*)(smem + SM_CNT);
    int*      sCk  = (int*)(smem + SM_CK);
    int*      sSx  = (int*)(smem + SM_SX);
    float*    sAx  = (float*)(smem + SM_AX);

    // ---- stage: token tid -> A-tile row tid (bf16), exact A = sum x^2 ----
    {
        const int t = tok0 + tid, b = t >> 12, hw = t & 4095;
        const float* xp = in + (b << 18) + hw;
        float A = 0.0f;
        #pragma unroll
        for (int dd = 0; dd < 32; dd++) {
            float f0 = xp[(2 * dd) << 12];
            float f1 = xp[(2 * dd + 1) << 12];
            A = __fadd_rn(A, __fmul_rn(f0, f0));
            A = __fadd_rn(A, __fmul_rn(f1, f1));
            __nv_bfloat162 p = __floats2bfloat162_rn(f0, f1);
            *(unsigned*)(smem + SM_A + tid * 144 + dd * 4) = *(unsigned*)&p;
        }
        sAx[tid] = A;
    }
    // ---- stage B (pre-packed bf16(-2w)) + C + zero hist/counters ----
    for (int i = tid; i < K_CODES * 32; i += TPB) {
        int k = i >> 5, dd = i & 31;
        *(unsigned*)(smem + SM_B + k * 144 + dd * 4) = g_wb16[i];
    }
    for (int i = tid; i < K_CODES; i += TPB) { sC[i] = g_C[i]; sH[i] = 0u; }
    sCnt[tid] = 0u;
    __syncthreads();

    // ---- load A fragments once (warp: tokens wid*32 .. +31) ----
    const int wbase = wid * 32;
    unsigned af[2][4][4];
    #pragma unroll
    for (int mt = 0; mt < 2; mt++)
        #pragma unroll
        for (int kt = 0; kt < 4; kt++) {
            unsigned aa = sbase + SM_A
                        + (unsigned)(wbase + mt * 16 + (lane & 15)) * 144u
                        + (unsigned)(kt * 32 + ((lane >> 4) & 1) * 16);
            ldsm4(af[mt][kt], aa);
        }

    const float2* sC2 = (const float2*)(smem + SM_C);

    // ---- pass 1: exact per-row FINAL min of bf16 scores ----
    float rm[4] = {3.4e38f, 3.4e38f, 3.4e38f, 3.4e38f};
    for (int nt = 0; nt < 64; nt++) {
        float s[8];
        score_nt(nt, af, sbase, sC2, lane, s);
        rm[0] = fminf(rm[0], fminf(s[0], s[1]));
        rm[1] = fminf(rm[1], fminf(s[2], s[3]));
        rm[2] = fminf(rm[2], fminf(s[4], s[5]));
        rm[3] = fminf(rm[3], fminf(s[6], s[7]));
    }
    float th[4];
    #pragma unroll
    for (int i = 0; i < 4; i++) {   // reduce over the 4 lanes sharing each row
        rm[i] = fminf(rm[i], __shfl_xor_sync(0xffffffffu, rm[i], 1));
        rm[i] = fminf(rm[i], __shfl_xor_sync(0xffffffffu, rm[i], 2));
        th[i] = rm[i] + MARGIN;
    }

    // ---- pass 2: recompute identical scores, collect candidates ----
    const int r0 = lane >> 2;
    const int tA = wbase + r0, tB = tA + 8, tC = wbase + 16 + r0, tD = tC + 8;
    for (int nt = 0; nt < 64; nt++) {
        float s[8];
        score_nt(nt, af, sbase, sC2, lane, s);
        const int k0 = nt * 8 + 2 * (lane & 3);
        #define PUSH(val, thr, tok, kk)                                   \
            if ((val) < (thr)) {                                          \
                unsigned p_ = atomicAdd(&sCnt[tok], 1u);                  \
                if (p_ < CAP) sCk[(tok) * CAP + p_] = (kk);               \
            }
        PUSH(s[0], th[0], tA, k0)     PUSH(s[1], th[0], tA, k0 + 1)
        PUSH(s[2], th[1], tB, k0)     PUSH(s[3], th[1], tB, k0 + 1)
        PUSH(s[4], th[2], tC, k0)     PUSH(s[5], th[2], tC, k0 + 1)
        PUSH(s[6], th[3], tD, k0)     PUSH(s[7], th[3], tD, k0 + 1)
        #undef PUSH
    }
    __syncthreads();

    // ---- exact refinement: token tid, reference-rounded distances ----
    {
        const int t = tok0 + tid, b = t >> 12, hw = t & 4095;
        const float* xp = in + (b << 18) + hw;
        float x[DIM];
        #pragma unroll
        for (int d = 0; d < DIM; d++) x[d] = xp[d << 12];
        const float A = sAx[tid];

        float bestd = 3.4e38f;
        int   bidx  = 1 << 30;
        const unsigned cn = sCnt[tid];

        #define EXACT(kk)                                                  \
        {                                                                  \
            const float4* wr = (const float4*)(wt + (kk) * DIM);           \
            float dot = 0.0f;                                              \
            _Pragma("unroll")                                              \
            for (int q = 0; q < 16; q++) {                                 \
                float4 v = wr[q];                                          \
                dot = __fmaf_rn(x[4 * q],     v.x, dot);                   \
                dot = __fmaf_rn(x[4 * q + 1], v.y, dot);                   \
                dot = __fmaf_rn(x[4 * q + 2], v.z, dot);                   \
                dot = __fmaf_rn(x[4 * q + 3], v.w, dot);                   \
            }                                                              \
            float dist = __fadd_rn(__fadd_rn(A, -2.0f * dot), sC[kk]);     \
            if (dist < bestd || (dist == bestd && (kk) < bidx)) {          \
                bestd = dist; bidx = (kk);                                 \
            }                                                              \
        }
        if (cn <= CAP) {
            for (unsigned c = 0; c < cn; c++) { int k = sCk[tid * CAP + c]; EXACT(k) }
        } else {
            for (int k = 0; k < K_CODES; k++) EXACT(k)   // sound fallback
        }
        #undef EXACT
        sSx[tid] = bidx;
        atomicAdd(&sH[bidx], 1u);
    }
    __syncthreads();

    // ---- output (linear-view quirk) + loss partial ----
    float lsum = 0.0f;
    const long ob = (long)tok0 * DIM;
    for (int i = tid; i < TOKCTA * DIM; i += TPB) {
        int   tk = i >> 6, d = i & 63;
        int   k  = sSx[tk];
        float q  = wt[k * DIM + d];
        float xv = in[ob + i];
        out[ob + i] = q;
        float df = q - xv;
        lsum = fmaf(df, df, lsum);
    }
    #pragma unroll
    for (int o = 16; o > 0; o >>= 1) lsum += __shfl_xor_sync(0xffffffffu, lsum, o);
    float* red = (float*)(smem + SM_CK);   // candidates dead; reuse as scratch
    __syncthreads();
    if (lane == 0) red[wid] = lsum;
    __syncthreads();
    if (tid == 0) {
        float v = 0.0f;
        #pragma unroll
        for (int w = 0; w < 8; w++) v += red[w];
        atomicAdd(&g_sumsq, v);
    }
    for (int k = tid; k < K_CODES; k += TPB) {
        unsigned c = sH[k];
        if (c) atomicAdd(&g_counts[k], c);
    }

    // ---- fused final: last CTA computes loss + perplexity, resets globals ----
    __shared__ unsigned islast;
    __threadfence();
    __syncthreads();
    if (tid == 0) {
        unsigned v = atomicAdd(&g_done, 1u);
        islast = (v == NCTA - 1) ? 1u : 0u;
    }
    __syncthreads();
    if (islast) {
        // all other CTAs' g_counts/g_sumsq atomics are visible (fence-before-done)
        float term = 0.0f;
        #pragma unroll
        for (int j = 0; j < 2; j++) {
            unsigned c = g_counts[tid + j * TPB];
            float p = (float)c * (1.0f / (float)N_TOK);
            term += p * logf(p + 1e-10f);
        }
        #pragma unroll
        for (int o = 16; o > 0; o >>= 1) term += __shfl_xor_sync(0xffffffffu, term, o);
        if (lane == 0) red[wid] = term;
        __syncthreads();
        if (tid == 0) {
            float v = 0.0f;
            #pragma unroll
            for (int w = 0; w < 8; w++) v += red[w];
            out[M_ELEMS]     = 1.25f * (g_sumsq * (1.0f / (float)M_ELEMS));
            out[M_ELEMS + 1] = expf(-v);
            g_sumsq = 0.0f;           // reset for next graph replay
            g_done  = 0u;
        }
        g_counts[tid]       = 0u;
        g_counts[tid + TPB] = 0u;
    }
}

extern "C" void kernel_launch(void* const* d_in, const int* in_sizes, int n_in,
                              void* d_out, int out_size)
{
    const float* in  = (const float*)d_in[0];
    const float* wt  = (const float*)d_in[1];
    float*       out = (float*)d_out;

    cudaFuncSetAttribute(vq_main, cudaFuncAttributeMaxDynamicSharedMemorySize, SM_TOT);

    vq_setup<<<16, 32>>>(wt);
    vq_main<<<NCTA, TPB, SM_TOT>>>(in, wt, out);
}

// round 12
// speedup vs baseline: 7.4452x; 1.3112x over previous
#include <cuda_runtime.h>
#include <cuda_bf16.h>
#include <math.h>

#define N_TOK   131072
#define K_CODES 512
#define DIM     64
#define M_ELEMS (N_TOK * DIM)
#define TPB     512
#define TOKCTA  256
#define NCTA    (N_TOK / TOKCTA)     // 512
#define MARGIN  3.0e-3f              // >= 2x worst-case bf16 scoring error
#define CAP     16

// SMEM byte offsets (rows padded to 144B -> ldmatrix conflict-free)
#define SM_A    0                    // A tile: 256 rows x 144B (36864)
#define SM_B    36864                // B tile: 512 rows x 144B (73728)
#define SM_C    110592               // C fp32[512]
#define SM_H    112640               // hist u32[512]
#define SM_CNT  114688               // cand count u32[256] (+pad)
#define SM_CK   115712               // cand k i32[256][16] (16384)
#define SM_SX   132096               // sidx i32[256]
#define SM_AX   133120               // exact A fp32[256]
#define SM_RM   134144               // cross-warp row mins f32[8grp][2half][8r0][4] (2048)
#define SM_TOT  136192

__device__ float    g_sumsq;               // zeroed at load; last CTA re-zeroes
__device__ unsigned g_counts[K_CODES];
__device__ unsigned g_done;                // completion counter (last-CTA pattern)
__device__ unsigned g_wb16[K_CODES * 32];  // bf16x2 of (-2*w), pairs along d
__device__ float    g_C[K_CODES];          // exact ||w_k||^2 (sequential rounded)

__device__ __forceinline__ void ldsm4(unsigned* r, unsigned addr) {
    asm volatile("ldmatrix.sync.aligned.m8n8.x4.shared.b16 {%0,%1,%2,%3}, [%4];"
                 : "=r"(r[0]), "=r"(r[1]), "=r"(r[2]), "=r"(r[3]) : "r"(addr));
}
__device__ __forceinline__ void mma16816(float* c, const unsigned* a,
                                         unsigned b0, unsigned b1) {
    asm volatile("mma.sync.aligned.m16n8k16.row.col.f32.bf16.bf16.f32 "
                 "{%0,%1,%2,%3}, {%4,%5,%6,%7}, {%8,%9}, {%0,%1,%2,%3};"
                 : "+f"(c[0]), "+f"(c[1]), "+f"(c[2]), "+f"(c[3])
                 : "r"(a[0]), "r"(a[1]), "r"(a[2]), "r"(a[3]), "r"(b0), "r"(b1));
}

// ------------- setup: parallel (16 blocks x 32 thr, 1 thread = 1 code) -------------
__global__ void vq_setup(const float* __restrict__ wt) {
    int k = blockIdx.x * 32 + threadIdx.x;   // 512 codes
    float4 w4[16];
    const float4* wr = (const float4*)(wt + k * DIM);
    #pragma unroll
    for (int q = 0; q < 16; q++) w4[q] = wr[q];
    float s = 0.0f;
    #pragma unroll
    for (int q = 0; q < 16; q++) {           // exact: sequential rounded, d ascending
        s = __fadd_rn(s, __fmul_rn(w4[q].x, w4[q].x));
        s = __fadd_rn(s, __fmul_rn(w4[q].y, w4[q].y));
        s = __fadd_rn(s, __fmul_rn(w4[q].z, w4[q].z));
        s = __fadd_rn(s, __fmul_rn(w4[q].w, w4[q].w));
    }
    g_C[k] = s;
    #pragma unroll
    for (int q = 0; q < 16; q++) {
        __nv_bfloat162 p0 = __floats2bfloat162_rn(-2.0f * w4[q].x, -2.0f * w4[q].y);
        __nv_bfloat162 p1 = __floats2bfloat162_rn(-2.0f * w4[q].z, -2.0f * w4[q].w);
        g_wb16[k * 32 + 2 * q]     = *(unsigned*)&p0;
        g_wb16[k * 32 + 2 * q + 1] = *(unsigned*)&p1;
    }
}

// per-n-tile score computation: 8 scores (2 m-tiles x {2 rows x 2 cols})
__device__ __forceinline__ void score_nt(int nt, const unsigned (&af)[2][4][4],
                                         unsigned sbase, const float2* sC2,
                                         int lane, float* s) {
    unsigned bf[8];
    unsigned ba = sbase + SM_B + (unsigned)(nt * 8 + (lane & 7)) * 144u
                  + (unsigned)((lane >> 3) & 3) * 16u;
    ldsm4(bf, ba);           // k 0..31
    ldsm4(bf + 4, ba + 64);  // k 32..63
    float2 cv = sC2[nt * 4 + (lane & 3)];
    float c0[4] = {cv.x, cv.y, cv.x, cv.y};
    float c1[4] = {cv.x, cv.y, cv.x, cv.y};
    #pragma unroll
    for (int kt = 0; kt < 4; kt++) {
        mma16816(c0, af[0][kt], bf[2 * kt], bf[2 * kt + 1]);
        mma16816(c1, af[1][kt], bf[2 * kt], bf[2 * kt + 1]);
    }
    s[0] = c0[0]; s[1] = c0[1]; s[2] = c0[2]; s[3] = c0[3];
    s[4] = c1[0]; s[5] = c1[1]; s[6] = c1[2]; s[7] = c1[3];
}

// ---------------- main: 16 warps, warp-pair splits the nt range ----------------
extern "C" __global__ void __launch_bounds__(TPB, 1)
vq_main(const float* __restrict__ in, const float* __restrict__ wt,
        float* __restrict__ out)
{
    extern __shared__ char smem[];
    const unsigned sbase = (unsigned)__cvta_generic_to_shared(smem);
    const int tid = threadIdx.x, wid = tid >> 5, lane = tid & 31;
    const int grp = wid >> 1;            // token group 0..7 (32 tokens each)
    const int hf  = wid & 1;             // nt half: 0 -> 0..31, 1 -> 32..63
    const int tok0 = blockIdx.x * TOKCTA;

    float*    sC   = (float*)(smem + SM_C);
    unsigned* sH   = (unsigned*)(smem + SM_H);
    unsigned* sCnt = (unsigned*)(smem + SM_CNT);
    int*      sCk  = (int*)(smem + SM_CK);
    int*      sSx  = (int*)(smem + SM_SX);
    float*    sAx  = (float*)(smem + SM_AX);
    float*    sRM  = (float*)(smem + SM_RM);

    // ---- stage: tid<256 -> token tid (bf16 A row + exact A = sum x^2) ----
    if (tid < TOKCTA) {
        const int t = tok0 + tid, b = t >> 12, hw = t & 4095;
        const float* xp = in + (b << 18) + hw;
        float A = 0.0f;
        #pragma unroll
        for (int dd = 0; dd < 32; dd++) {
            float f0 = xp[(2 * dd) << 12];
            float f1 = xp[(2 * dd + 1) << 12];
            A = __fadd_rn(A, __fmul_rn(f0, f0));
            A = __fadd_rn(A, __fmul_rn(f1, f1));
            __nv_bfloat162 p = __floats2bfloat162_rn(f0, f1);
            *(unsigned*)(smem + SM_A + tid * 144 + dd * 4) = *(unsigned*)&p;
        }
        sAx[tid] = A;
        sCnt[tid] = 0u;
    }
    // ---- stage B (pre-packed bf16(-2w)) + C + zero hist ----
    for (int i = tid; i < K_CODES * 32; i += TPB) {
        int k = i >> 5, dd = i & 31;
        *(unsigned*)(smem + SM_B + k * 144 + dd * 4) = g_wb16[i];
    }
    if (tid < K_CODES) { sC[tid] = g_C[tid]; sH[tid] = 0u; }
    __syncthreads();

    // ---- load A fragments (warp pair: same group, same fragments) ----
    const int wbase = grp * 32;
    unsigned af[2][4][4];
    #pragma unroll
    for (int mt = 0; mt < 2; mt++)
        #pragma unroll
        for (int kt = 0; kt < 4; kt++) {
            unsigned aa = sbase + SM_A
                        + (unsigned)(wbase + mt * 16 + (lane & 15)) * 144u
                        + (unsigned)(kt * 32 + ((lane >> 4) & 1) * 16);
            ldsm4(af[mt][kt], aa);
        }

    const float2* sC2 = (const float2*)(smem + SM_C);
    const int ntlo = hf * 32, nthi = ntlo + 32;
    const int r0 = lane >> 2;

    // ---- pass 1: per-row min over this warp's nt half ----
    float rm[4] = {3.4e38f, 3.4e38f, 3.4e38f, 3.4e38f};
    for (int nt = ntlo; nt < nthi; nt++) {
        float s[8];
        score_nt(nt, af, sbase, sC2, lane, s);
        rm[0] = fminf(rm[0], fminf(s[0], s[1]));
        rm[1] = fminf(rm[1], fminf(s[2], s[3]));
        rm[2] = fminf(rm[2], fminf(s[4], s[5]));
        rm[3] = fminf(rm[3], fminf(s[6], s[7]));
    }
    #pragma unroll
    for (int i = 0; i < 4; i++) {   // reduce over the 4 lanes sharing each row
        rm[i] = fminf(rm[i], __shfl_xor_sync(0xffffffffu, rm[i], 1));
        rm[i] = fminf(rm[i], __shfl_xor_sync(0xffffffffu, rm[i], 2));
    }
    // cross-warp (pair) combine via smem
    if ((lane & 3) == 0) {
        #pragma unroll
        for (int i = 0; i < 4; i++)
            sRM[((grp * 2 + hf) * 8 + r0) * 4 + i] = rm[i];
    }
    __syncthreads();
    float th[4];
    #pragma unroll
    for (int i = 0; i < 4; i++) {
        float o = sRM[((grp * 2 + (hf ^ 1)) * 8 + r0) * 4 + i];
        rm[i] = fminf(rm[i], o);
        th[i] = rm[i] + MARGIN;      // FINAL row min + margin
    }

    // ---- pass 2: recompute this half's scores, collect candidates ----
    const int tA = wbase + r0, tB = tA + 8, tC = wbase + 16 + r0, tD = tC + 8;
    for (int nt = ntlo; nt < nthi; nt++) {
        float s[8];
        score_nt(nt, af, sbase, sC2, lane, s);
        const int k0 = nt * 8 + 2 * (lane & 3);
        #define PUSH(val, thr, tok, kk)                                   \
            if ((val) < (thr)) {                                          \
                unsigned p_ = atomicAdd(&sCnt[tok], 1u);                  \
                if (p_ < CAP) sCk[(tok) * CAP + p_] = (kk);               \
            }
        PUSH(s[0], th[0], tA, k0)     PUSH(s[1], th[0], tA, k0 + 1)
        PUSH(s[2], th[1], tB, k0)     PUSH(s[3], th[1], tB, k0 + 1)
        PUSH(s[4], th[2], tC, k0)     PUSH(s[5], th[2], tC, k0 + 1)
        PUSH(s[6], th[3], tD, k0)     PUSH(s[7], th[3], tD, k0 + 1)
        #undef PUSH
    }
    __syncthreads();

    // ---- exact refinement: tid<256 handles token tid ----
    if (tid < TOKCTA) {
        const int t = tok0 + tid, b = t >> 12, hw = t & 4095;
        const float* xp = in + (b << 18) + hw;
        float x[DIM];
        #pragma unroll
        for (int d = 0; d < DIM; d++) x[d] = xp[d << 12];
        const float A = sAx[tid];

        float bestd = 3.4e38f;
        int   bidx  = 1 << 30;
        const unsigned cn = sCnt[tid];

        #define EXACT(kk)                                                  \
        {                                                                  \
            const float4* wr = (const float4*)(wt + (kk) * DIM);           \
            float dot = 0.0f;                                              \
            _Pragma("unroll")                                              \
            for (int q = 0; q < 16; q++) {                                 \
                float4 v = wr[q];                                          \
                dot = __fmaf_rn(x[4 * q],     v.x, dot);                   \
                dot = __fmaf_rn(x[4 * q + 1], v.y, dot);                   \
                dot = __fmaf_rn(x[4 * q + 2], v.z, dot);                   \
                dot = __fmaf_rn(x[4 * q + 3], v.w, dot);                   \
            }                                                              \
            float dist = __fadd_rn(__fadd_rn(A, -2.0f * dot), sC[kk]);     \
            if (dist < bestd || (dist == bestd && (kk) < bidx)) {          \
                bestd = dist; bidx = (kk);                                 \
            }                                                              \
        }
        if (cn <= CAP) {
            for (unsigned c = 0; c < cn; c++) { int k = sCk[tid * CAP + c]; EXACT(k) }
        } else {
            for (int k = 0; k < K_CODES; k++) EXACT(k)   // sound fallback
        }
        #undef EXACT
        sSx[tid] = bidx;
        atomicAdd(&sH[bidx], 1u);
    }
    __syncthreads();

    // ---- output (linear-view quirk) + loss partial ----
    float lsum = 0.0f;
    const long ob = (long)tok0 * DIM;
    for (int i = tid; i < TOKCTA * DIM; i += TPB) {
        int   tk = i >> 6, d = i & 63;
        int   k  = sSx[tk];
        float q  = wt[k * DIM + d];
        float xv = in[ob + i];
        out[ob + i] = q;
        float df = q - xv;
        lsum = fmaf(df, df, lsum);
    }
    #pragma unroll
    for (int o = 16; o > 0; o >>= 1) lsum += __shfl_xor_sync(0xffffffffu, lsum, o);
    float* red = (float*)(smem + SM_CK);   // candidates dead; reuse as scratch
    __syncthreads();
    if (lane == 0) red[wid] = lsum;
    __syncthreads();
    if (tid == 0) {
        float v = 0.0f;
        #pragma unroll
        for (int w = 0; w < 16; w++) v += red[w];
        atomicAdd(&g_sumsq, v);
    }
    if (tid < K_CODES) {
        unsigned c = sH[tid];
        if (c) atomicAdd(&g_counts[tid], c);
    }

    // ---- fused final: last CTA computes loss + perplexity, resets globals ----
    __shared__ unsigned islast;
    __threadfence();
    __syncthreads();
    if (tid == 0) {
        unsigned v = atomicAdd(&g_done, 1u);
        islast = (v == NCTA - 1) ? 1u : 0u;
    }
    __syncthreads();
    if (islast) {
        unsigned c = g_counts[tid];          // tid 0..511 = one code each
        float p = (float)c * (1.0f / (float)N_TOK);
        float term = p * logf(p + 1e-10f);
        #pragma unroll
        for (int o = 16; o > 0; o >>= 1) term += __shfl_xor_sync(0xffffffffu, term, o);
        if (lane == 0) red[wid] = term;
        __syncthreads();
        if (tid == 0) {
            float v = 0.0f;
            #pragma unroll
            for (int w = 0; w < 16; w++) v += red[w];
            out[M_ELEMS]     = 1.25f * (g_sumsq * (1.0f / (float)M_ELEMS));
            out[M_ELEMS + 1] = expf(-v);
            g_sumsq = 0.0f;                  // reset for next graph replay
            g_done  = 0u;
        }
        g_counts[tid] = 0u;
    }
}

extern "C" void kernel_launch(void* const* d_in, const int* in_sizes, int n_in,
                              void* d_out, int out_size)
{
    const float* in  = (const float*)d_in[0];
    const float* wt  = (const float*)d_in[1];
    float*       out = (float*)d_out;

    cudaFuncSetAttribute(vq_main, cudaFuncAttributeMaxDynamicSharedMemorySize, SM_TOT);

    vq_setup<<<16, 32>>>(wt);
    vq_main<<<NCTA, TPB, SM_TOT>>>(in, wt, out);
}